// round 7
// baseline (speedup 1.0000x reference)
#include <cuda_runtime.h>

// Problem shapes (fixed)
#define BB 32
#define NN 4096
#define DD 8
#define NEE 2048
#define DEE 4

// Device scratch (static globals; no allocation)
__device__ unsigned g_mask_int[NN];
__device__ unsigned g_mask_ext[NEE];
__device__ unsigned char g_del_int[NN];
__device__ unsigned char g_del_ext[NEE];
__device__ int g_list[BB][6784];    // combined: int entries [0,N), ext entries N+e, -1 pad
__device__ int g_cnt[BB];           // padded combined length (multiple of 16)

// ---------------------------------------------------------------------------
// Kernel 1: spike generation (thread per (b,n)) + delay decode + mask zero.
// ---------------------------------------------------------------------------
__global__ void k_spike(const float* __restrict__ V, const float* __restrict__ a,
                        const float* __restrict__ dmap_int,
                        const float* __restrict__ dmap_ext,
                        float* __restrict__ out) {
    int idx = blockIdx.x * blockDim.x + threadIdx.x;   // 0 .. B*N-1
    float v  = V[idx];
    float aa = a[idx];
    float th = __fadd_rn(1.0f, __fmul_rn(1.8f, aa));
    float x  = (__fadd_rn(v, -th) >= 0.0f) ? 1.0f : 0.0f;
    out[idx] = x;                                       // row 0: X
    out[2 * BB * NN + idx] = 0.98f * aa + x;            // row 2: a_new

    if (idx < NN) {
        int del = 0;
#pragma unroll
        for (int d = 0; d < DD; d++)
            if (dmap_int[d * NN + idx] > 0.5f) del = d;
        g_del_int[idx] = (unsigned char)del;
        g_mask_int[idx] = 0u;
    }
    if (idx < NEE) {
        int del = 0;
#pragma unroll
        for (int d = 0; d < DEE; d++)
            if (dmap_ext[d * NEE + idx] > 0.5f) del = d;
        g_del_ext[idx] = (unsigned char)del;
        g_mask_ext[idx] = 0u;
    }
}

// ---------------------------------------------------------------------------
// Kernel 2: mask build via predicated atomicOr (commutative -> deterministic).
// ---------------------------------------------------------------------------
__global__ void __launch_bounds__(256) k_mask2(
        const float* __restrict__ Xd, const float* __restrict__ Xext,
        const float* __restrict__ out /* row 0 = X */) {
    int i = blockIdx.x * blockDim.x + threadIdx.x;      // source 0..N-1
    int b = blockIdx.y;                                 // batch

    {
        int del = g_del_int[i];
        float xs = (del == 0) ? out[b * NN + i]
                              : Xd[(size_t)(del - 1) * BB * NN + b * NN + i];
        if (xs > 0.5f) atomicOr(&g_mask_int[i], 1u << b);
    }
    if (i < NEE) {
        int del = g_del_ext[i];
        float xs = Xext[(size_t)del * BB * NEE + b * NEE + i];
        if (xs > 0.5f) atomicOr(&g_mask_ext[i], 1u << b);
    }
}

// ---------------------------------------------------------------------------
// Kernel 3: compaction into ONE combined list per batch.
// Internal sources first (value = i), then external (value = N + i),
// total padded to a multiple of 16 with -1.
// ---------------------------------------------------------------------------
__global__ void __launch_bounds__(256) k_compact() {
    int b = blockIdx.x;            // 0..31
    int tid = threadIdx.x;
    int w = tid >> 5, lane = tid & 31;
    unsigned lt = (lane == 0) ? 0u : (0xffffffffu >> (32 - lane));

    __shared__ int wcnt[8], wbase[8], s_total, s_base_ext;

    // ---- internal ----
    {
        int cnt = 0;
#pragma unroll
        for (int r = 0; r < 16; r++) {
            int i = (w * 16 + r) * 32 + lane;
            bool act = (g_mask_int[i] >> b) & 1u;
            cnt += __popc(__ballot_sync(0xffffffffu, act));
        }
        if (lane == 0) wcnt[w] = cnt;
        __syncthreads();
        if (tid == 0) {
            int s = 0;
#pragma unroll
            for (int j = 0; j < 8; j++) { wbase[j] = s; s += wcnt[j]; }
            s_total = s;
            s_base_ext = s;      // ext entries appended right after int entries
        }
        __syncthreads();
        int base = wbase[w];
#pragma unroll
        for (int r = 0; r < 16; r++) {
            int i = (w * 16 + r) * 32 + lane;
            bool act = (g_mask_int[i] >> b) & 1u;
            unsigned bal = __ballot_sync(0xffffffffu, act);
            if (act) g_list[b][base + __popc(bal & lt)] = i;
            base += __popc(bal);
        }
        __syncthreads();
    }

    // ---- external (appended) ----
    {
        int cnt = 0;
#pragma unroll
        for (int r = 0; r < 8; r++) {
            int i = (w * 8 + r) * 32 + lane;
            bool act = (g_mask_ext[i] >> b) & 1u;
            cnt += __popc(__ballot_sync(0xffffffffu, act));
        }
        if (lane == 0) wcnt[w] = cnt;
        __syncthreads();
        if (tid == 0) {
            int s = s_base_ext;
#pragma unroll
            for (int j = 0; j < 8; j++) { wbase[j] = s; s += wcnt[j]; }
            s_total = s;
        }
        __syncthreads();
        int base = wbase[w];
#pragma unroll
        for (int r = 0; r < 8; r++) {
            int i = (w * 8 + r) * 32 + lane;
            bool act = (g_mask_ext[i] >> b) & 1u;
            unsigned bal = __ballot_sync(0xffffffffu, act);
            if (act) g_list[b][base + __popc(bal & lt)] = NN + i;
            base += __popc(bal);
        }
        __syncthreads();
        int t = s_total;
        int padded = (t + 15) & ~15;
        if (t + tid < padded) g_list[b][t + tid] = -1;
        if (tid == 0) g_cnt[b] = padded;
    }
}

// ---------------------------------------------------------------------------
// Kernel 4: cp.async-pipelined sparse row-gather + membrane update.
// 4 stages x 16 sources; loads land in smem via LDGSTS so in-flight depth
// (48 loads/thread) is structural, independent of the register allocator.
// Each thread copies and consumes only its own smem cells -> no block sync
// in the steady loop. Sentinels (-1) zero-fill via src-size=0.
// ---------------------------------------------------------------------------
#define NSTAGES 4
#define SRC_PER_STAGE 16

__global__ void __launch_bounds__(128) k_gather(
        const float* __restrict__ V,
        const float* __restrict__ W_int,
        const float* __restrict__ W_ext,
        float* __restrict__ out) {
    __shared__ float s_buf[NSTAGES][SRC_PER_STAGE][128];

    const int b = blockIdx.y;
    const int cnt = g_cnt[b];
    const int nwin = cnt / SRC_PER_STAGE;
    const int* __restrict__ lst = g_list[b];

    const int n = blockIdx.x * 128 + threadIdx.x;    // column
    const int idx = b * NN + n;

    unsigned sbase = (unsigned)__cvta_generic_to_shared(&s_buf[0][0][0]);
    const float* Wi = W_int + n;
    const float* We = W_ext + n;

    // issue one stage: 16 cp.asyncs + commit
    auto issue = [&](int st, int k) {
#pragma unroll
        for (int u = 0; u < SRC_PER_STAGE; u++) {
            int e = __ldg(lst + k + u);
            int valid = (e >= 0) ? 4 : 0;
            int ec = (e < 0) ? 0 : e;
            const float* src = (ec < NN) ? (Wi + (size_t)ec * NN)
                                         : (We + (size_t)(ec - NN) * NN);
            unsigned saddr = sbase + ((st * SRC_PER_STAGE + u) * 128 + threadIdx.x) * 4u;
            asm volatile("cp.async.ca.shared.global [%0], [%1], 4, %2;"
                         :: "r"(saddr), "l"(src), "r"(valid));
        }
        asm volatile("cp.async.commit_group;" ::: "memory");
    };

    float x = out[idx];                       // X (row 0)
    float acc0 = 0.95f * V[idx] * (1.0f - x);
    float acc1 = 0.0f, acc2 = 0.0f, acc3 = 0.0f;

    // prologue: 3 stages in flight
#pragma unroll
    for (int s = 0; s < NSTAGES - 1; s++) {
        if (s < nwin) issue(s, s * SRC_PER_STAGE);
        else asm volatile("cp.async.commit_group;" ::: "memory");
    }

    for (int kw = 0; kw < nwin; kw++) {
        asm volatile("cp.async.wait_group %0;" :: "n"(NSTAGES - 2) : "memory");
        int st = kw & (NSTAGES - 1);
        // consume stage st
#pragma unroll
        for (int u = 0; u < SRC_PER_STAGE; u += 4) {
            float w0 = s_buf[st][u + 0][threadIdx.x];
            float w1 = s_buf[st][u + 1][threadIdx.x];
            float w2 = s_buf[st][u + 2][threadIdx.x];
            float w3 = s_buf[st][u + 3][threadIdx.x];
            acc0 += w0; acc1 += w1; acc2 += w2; acc3 += w3;
        }
        // issue next stage (buffer reuse distance = NSTAGES)
        int kn = kw + NSTAGES - 1;
        if (kn < nwin) issue(kn & (NSTAGES - 1), kn * SRC_PER_STAGE);
        else asm volatile("cp.async.commit_group;" ::: "memory");
    }

    out[BB * NN + idx] = (acc0 + acc1) + (acc2 + acc3);   // row 1: V_new
}

// ---------------------------------------------------------------------------
extern "C" void kernel_launch(void* const* d_in, const int* in_sizes, int n_in,
                              void* d_out, int out_size) {
    const float* V        = (const float*)d_in[0];   // [B,N]
    const float* a        = (const float*)d_in[1];   // [B,N]
    const float* Xd       = (const float*)d_in[2];   // [D,B,N]
    const float* Xext     = (const float*)d_in[3];   // [DE,B,NE]
    const float* W_int    = (const float*)d_in[4];   // [N,N]
    const float* W_ext    = (const float*)d_in[5];   // [NE,N]
    const float* dmap_int = (const float*)d_in[6];   // [D,N]
    const float* dmap_ext = (const float*)d_in[7];   // [DE,NE]
    float* out = (float*)d_out;                      // [3,B,N]

    k_spike<<<(BB * NN) / 256, 256>>>(V, a, dmap_int, dmap_ext, out);
    dim3 mgrid(NN / 256, BB);
    k_mask2<<<mgrid, 256>>>(Xd, Xext, out);
    k_compact<<<BB, 256>>>();
    dim3 grid(NN / 128, BB);
    k_gather<<<grid, 128>>>(V, W_int, W_ext, out);
}

// round 8
// speedup vs baseline: 1.1902x; 1.1902x over previous
#include <cuda_runtime.h>

// Problem shapes (fixed)
#define BB 32
#define NN 4096
#define DD 8
#define NEE 2048
#define DEE 4
#define NSPLIT 4

// Device scratch (static globals; no allocation)
__device__ unsigned g_mask_int[NN];
__device__ unsigned g_mask_ext[NEE];
__device__ unsigned char g_del_int[NN];
__device__ unsigned char g_del_ext[NEE];
__device__ int g_list[BB][6784];    // combined: int entries [0,N), ext N+e, -1 pad
__device__ int g_cnt[BB];           // padded combined length (multiple of 16)
__device__ float g_part[NSPLIT][BB][NN];   // split-K partial sums

// ---------------------------------------------------------------------------
// Kernel 1: spike generation (thread per (b,n)) + delay decode + mask zero.
// ---------------------------------------------------------------------------
__global__ void k_spike(const float* __restrict__ V, const float* __restrict__ a,
                        const float* __restrict__ dmap_int,
                        const float* __restrict__ dmap_ext,
                        float* __restrict__ out) {
    int idx = blockIdx.x * blockDim.x + threadIdx.x;   // 0 .. B*N-1
    float v  = V[idx];
    float aa = a[idx];
    float th = __fadd_rn(1.0f, __fmul_rn(1.8f, aa));
    float x  = (__fadd_rn(v, -th) >= 0.0f) ? 1.0f : 0.0f;
    out[idx] = x;                                       // row 0: X
    out[2 * BB * NN + idx] = 0.98f * aa + x;            // row 2: a_new

    if (idx < NN) {
        int del = 0;
#pragma unroll
        for (int d = 0; d < DD; d++)
            if (dmap_int[d * NN + idx] > 0.5f) del = d;
        g_del_int[idx] = (unsigned char)del;
        g_mask_int[idx] = 0u;
    }
    if (idx < NEE) {
        int del = 0;
#pragma unroll
        for (int d = 0; d < DEE; d++)
            if (dmap_ext[d * NEE + idx] > 0.5f) del = d;
        g_del_ext[idx] = (unsigned char)del;
        g_mask_ext[idx] = 0u;
    }
}

// ---------------------------------------------------------------------------
// Kernel 2: mask build via predicated atomicOr (commutative -> deterministic).
// ---------------------------------------------------------------------------
__global__ void __launch_bounds__(256) k_mask2(
        const float* __restrict__ Xd, const float* __restrict__ Xext,
        const float* __restrict__ out /* row 0 = X */) {
    int i = blockIdx.x * blockDim.x + threadIdx.x;      // source 0..N-1
    int b = blockIdx.y;                                 // batch

    {
        int del = g_del_int[i];
        float xs = (del == 0) ? out[b * NN + i]
                              : Xd[(size_t)(del - 1) * BB * NN + b * NN + i];
        if (xs > 0.5f) atomicOr(&g_mask_int[i], 1u << b);
    }
    if (i < NEE) {
        int del = g_del_ext[i];
        float xs = Xext[(size_t)del * BB * NEE + b * NEE + i];
        if (xs > 0.5f) atomicOr(&g_mask_ext[i], 1u << b);
    }
}

// ---------------------------------------------------------------------------
// Kernel 3: compaction into ONE combined list per batch (int first, then
// N+ext), padded to a multiple of 16 with -1.
// ---------------------------------------------------------------------------
__global__ void __launch_bounds__(256) k_compact() {
    int b = blockIdx.x;            // 0..31
    int tid = threadIdx.x;
    int w = tid >> 5, lane = tid & 31;
    unsigned lt = (lane == 0) ? 0u : (0xffffffffu >> (32 - lane));

    __shared__ int wcnt[8], wbase[8], s_total, s_base_ext;

    // ---- internal ----
    {
        int cnt = 0;
#pragma unroll
        for (int r = 0; r < 16; r++) {
            int i = (w * 16 + r) * 32 + lane;
            bool act = (g_mask_int[i] >> b) & 1u;
            cnt += __popc(__ballot_sync(0xffffffffu, act));
        }
        if (lane == 0) wcnt[w] = cnt;
        __syncthreads();
        if (tid == 0) {
            int s = 0;
#pragma unroll
            for (int j = 0; j < 8; j++) { wbase[j] = s; s += wcnt[j]; }
            s_total = s;
            s_base_ext = s;
        }
        __syncthreads();
        int base = wbase[w];
#pragma unroll
        for (int r = 0; r < 16; r++) {
            int i = (w * 16 + r) * 32 + lane;
            bool act = (g_mask_int[i] >> b) & 1u;
            unsigned bal = __ballot_sync(0xffffffffu, act);
            if (act) g_list[b][base + __popc(bal & lt)] = i;
            base += __popc(bal);
        }
        __syncthreads();
    }

    // ---- external (appended) ----
    {
        int cnt = 0;
#pragma unroll
        for (int r = 0; r < 8; r++) {
            int i = (w * 8 + r) * 32 + lane;
            bool act = (g_mask_ext[i] >> b) & 1u;
            cnt += __popc(__ballot_sync(0xffffffffu, act));
        }
        if (lane == 0) wcnt[w] = cnt;
        __syncthreads();
        if (tid == 0) {
            int s = s_base_ext;
#pragma unroll
            for (int j = 0; j < 8; j++) { wbase[j] = s; s += wcnt[j]; }
            s_total = s;
        }
        __syncthreads();
        int base = wbase[w];
#pragma unroll
        for (int r = 0; r < 8; r++) {
            int i = (w * 8 + r) * 32 + lane;
            bool act = (g_mask_ext[i] >> b) & 1u;
            unsigned bal = __ballot_sync(0xffffffffu, act);
            if (act) g_list[b][base + __popc(bal & lt)] = NN + i;
            base += __popc(bal);
        }
        __syncthreads();
        int t = s_total;
        int padded = (t + 15) & ~15;
        if (t + tid < padded) g_list[b][t + tid] = -1;
        if (tid == 0) g_cnt[b] = padded;
    }
}

// ---------------------------------------------------------------------------
// Kernel 4: split-K sparse row-gather. grid (N/128, B, NSPLIT).
// Split s handles windows s, s+NSPLIT, s+2*NSPLIT, ... of 16 sources each.
// No smem (occupancy!); list read via __ldg (warp-uniform, L1-hot).
// Partials written to g_part (fixed-order combine later => deterministic).
// ---------------------------------------------------------------------------
__global__ void k_gather(const float* __restrict__ W_int,
                         const float* __restrict__ W_ext,
                         float* __restrict__ out) {
    const int b = blockIdx.y;
    const int s = blockIdx.z;
    const int nwin = g_cnt[b] / 16;
    const int* __restrict__ lst = g_list[b];

    const int n = blockIdx.x * 128 + threadIdx.x;    // column
    const float* Wi = W_int + n;
    const float* We = W_ext + n;

    float acc0 = 0.0f, acc1 = 0.0f, acc2 = 0.0f, acc3 = 0.0f;

    for (int j = s; j < nwin; j += NSPLIT) {
        const int k = j * 16;
        int e[16];
#pragma unroll
        for (int u = 0; u < 16; u++) e[u] = __ldg(lst + k + u);
        float w[16];
#pragma unroll
        for (int u = 0; u < 16; u++) {
            int ec = (e[u] < 0) ? 0 : e[u];
            const float* src = (ec < NN) ? (Wi + (size_t)ec * NN)
                                         : (We + (size_t)(ec - NN) * NN);
            w[u] = (e[u] >= 0) ? __ldg(src) : 0.0f;
        }
#pragma unroll
        for (int u = 0; u < 16; u += 4) {
            acc0 += w[u]; acc1 += w[u + 1]; acc2 += w[u + 2]; acc3 += w[u + 3];
        }
    }

    g_part[s][b][n] = (acc0 + acc1) + (acc2 + acc3);
}

// ---------------------------------------------------------------------------
// Kernel 5: combine partials + leak/reset term -> V_new (row 1).
// Fixed summation order => deterministic.
// ---------------------------------------------------------------------------
__global__ void k_combine(const float* __restrict__ V, float* __restrict__ out) {
    int idx = blockIdx.x * blockDim.x + threadIdx.x;   // 0 .. B*N-1
    int b = idx / NN, n = idx - b * NN;
    float x = out[idx];                                 // X (row 0)
    float acc = 0.95f * V[idx] * (1.0f - x);
    acc += g_part[0][b][n];
    acc += g_part[1][b][n];
    acc += g_part[2][b][n];
    acc += g_part[3][b][n];
    out[BB * NN + idx] = acc;                           // row 1: V_new
}

// ---------------------------------------------------------------------------
extern "C" void kernel_launch(void* const* d_in, const int* in_sizes, int n_in,
                              void* d_out, int out_size) {
    const float* V        = (const float*)d_in[0];   // [B,N]
    const float* a        = (const float*)d_in[1];   // [B,N]
    const float* Xd       = (const float*)d_in[2];   // [D,B,N]
    const float* Xext     = (const float*)d_in[3];   // [DE,B,NE]
    const float* W_int    = (const float*)d_in[4];   // [N,N]
    const float* W_ext    = (const float*)d_in[5];   // [NE,N]
    const float* dmap_int = (const float*)d_in[6];   // [D,N]
    const float* dmap_ext = (const float*)d_in[7];   // [DE,NE]
    float* out = (float*)d_out;                      // [3,B,N]

    k_spike<<<(BB * NN) / 256, 256>>>(V, a, dmap_int, dmap_ext, out);
    dim3 mgrid(NN / 256, BB);
    k_mask2<<<mgrid, 256>>>(Xd, Xext, out);
    k_compact<<<BB, 256>>>();
    dim3 grid(NN / 128, BB, NSPLIT);
    k_gather<<<grid, 128>>>(W_int, W_ext, out);
    k_combine<<<(BB * NN) / 256, 256>>>(V, out);
}

// round 9
// speedup vs baseline: 1.4866x; 1.2490x over previous
#include <cuda_runtime.h>

// Problem shapes (fixed)
#define BB 32
#define NN 4096
#define DD 8
#define NEE 2048
#define DEE 4
#define NSPLIT 4

// Device scratch (static globals; no allocation). All zero-initialized at
// module load; every kernel_launch call leaves masks zeroed again (k_combine),
// so the sequence is deterministic call-to-call.
__device__ unsigned g_mask_int[NN];
__device__ unsigned g_mask_ext[NEE];
__device__ long long g_list[BB][6784];   // premultiplied byte offsets rel. W_int
__device__ int g_cnt[BB];                // padded combined length (multiple of 16)
__device__ float g_part[NSPLIT][BB][NN]; // split-K partial sums
__device__ float g_zero[NN];             // stays all-zero; pad rows point here

// ---------------------------------------------------------------------------
// Kernel 1 (fused spike + mask): thread per (b,n).
// X = (V - (1 + 1.8 a) >= 0); a_new = 0.98 a + X  (rows 0 and 2).
// Delay-selected spike for THIS thread's source: del==0 uses the locally
// computed x (no cross-thread dependency), else reads input Xd. Sets the
// batch bit via atomicOr (commutative -> deterministic). Ext sources ride on
// threads with n < NE of batch b.
// ---------------------------------------------------------------------------
__global__ void k_spikemask(const float* __restrict__ V, const float* __restrict__ a,
                            const float* __restrict__ Xd, const float* __restrict__ Xext,
                            const float* __restrict__ dmap_int,
                            const float* __restrict__ dmap_ext,
                            float* __restrict__ out) {
    int idx = blockIdx.x * blockDim.x + threadIdx.x;   // 0 .. B*N-1
    int b = idx >> 12;                                 // idx / NN
    int n = idx & (NN - 1);

    float v  = V[idx];
    float aa = a[idx];
    float th = __fadd_rn(1.0f, __fmul_rn(1.8f, aa));
    float x  = (__fadd_rn(v, -th) >= 0.0f) ? 1.0f : 0.0f;
    out[idx] = x;                                       // row 0: X
    out[2 * BB * NN + idx] = 0.98f * aa + x;            // row 2: a_new

    // internal source (b, n)
    {
        int del = 0;
#pragma unroll
        for (int d = 0; d < DD; d++)
            if (dmap_int[d * NN + n] > 0.5f) del = d;
        float xs = (del == 0) ? x : Xd[(size_t)(del - 1) * BB * NN + idx];
        if (xs > 0.5f) atomicOr(&g_mask_int[n], 1u << b);
    }
    // external source (b, n) for n < NE
    if (n < NEE) {
        int del = 0;
#pragma unroll
        for (int d = 0; d < DEE; d++)
            if (dmap_ext[d * NEE + n] > 0.5f) del = d;
        float xs = Xext[(size_t)del * BB * NEE + b * NEE + n];
        if (xs > 0.5f) atomicOr(&g_mask_ext[n], 1u << b);
    }
}

// ---------------------------------------------------------------------------
// Kernel 2: compaction into ONE combined offset list per batch.
// Entries are 64-bit byte offsets relative to W_int:
//   internal i -> i*N*4 ; external j -> (W_ext - W_int) + j*N*4 ;
//   padding    -> (g_zero - W_int)  (loads read zeros; no predicates needed).
// Padded to a multiple of 16.
// ---------------------------------------------------------------------------
__global__ void __launch_bounds__(256) k_compact(const float* __restrict__ W_int,
                                                 const float* __restrict__ W_ext) {
    int b = blockIdx.x;            // 0..31
    int tid = threadIdx.x;
    int w = tid >> 5, lane = tid & 31;
    unsigned lt = (lane == 0) ? 0u : (0xffffffffu >> (32 - lane));

    const long long ext_base = (long long)((const char*)W_ext - (const char*)W_int);
    const long long zero_off = (long long)((const char*)g_zero - (const char*)W_int);

    __shared__ int wcnt[8], wbase[8], s_total, s_base_ext;

    // ---- internal ----
    {
        int cnt = 0;
#pragma unroll
        for (int r = 0; r < 16; r++) {
            int i = (w * 16 + r) * 32 + lane;
            bool act = (g_mask_int[i] >> b) & 1u;
            cnt += __popc(__ballot_sync(0xffffffffu, act));
        }
        if (lane == 0) wcnt[w] = cnt;
        __syncthreads();
        if (tid == 0) {
            int s = 0;
#pragma unroll
            for (int j = 0; j < 8; j++) { wbase[j] = s; s += wcnt[j]; }
            s_total = s;
            s_base_ext = s;
        }
        __syncthreads();
        int base = wbase[w];
#pragma unroll
        for (int r = 0; r < 16; r++) {
            int i = (w * 16 + r) * 32 + lane;
            bool act = (g_mask_int[i] >> b) & 1u;
            unsigned bal = __ballot_sync(0xffffffffu, act);
            if (act) g_list[b][base + __popc(bal & lt)] = (long long)i * (NN * 4);
            base += __popc(bal);
        }
        __syncthreads();
    }

    // ---- external (appended) ----
    {
        int cnt = 0;
#pragma unroll
        for (int r = 0; r < 8; r++) {
            int i = (w * 8 + r) * 32 + lane;
            bool act = (g_mask_ext[i] >> b) & 1u;
            cnt += __popc(__ballot_sync(0xffffffffu, act));
        }
        if (lane == 0) wcnt[w] = cnt;
        __syncthreads();
        if (tid == 0) {
            int s = s_base_ext;
#pragma unroll
            for (int j = 0; j < 8; j++) { wbase[j] = s; s += wcnt[j]; }
            s_total = s;
        }
        __syncthreads();
        int base = wbase[w];
#pragma unroll
        for (int r = 0; r < 8; r++) {
            int i = (w * 8 + r) * 32 + lane;
            bool act = (g_mask_ext[i] >> b) & 1u;
            unsigned bal = __ballot_sync(0xffffffffu, act);
            if (act) g_list[b][base + __popc(bal & lt)] = ext_base + (long long)i * (NN * 4);
            base += __popc(bal);
        }
        __syncthreads();
        int t = s_total;
        int padded = (t + 15) & ~15;
        if (t + tid < padded) g_list[b][t + tid] = zero_off;
        if (tid == 0) g_cnt[b] = padded;
    }
}

// ---------------------------------------------------------------------------
// Kernel 3: split-K sparse row-gather, float2 per thread.
// grid (N/256, B, NSPLIT), 128 threads. Inner step per source:
//   LDG.64 offset (warp-uniform, L1-hot) -> 64-bit add -> LDG.64 W -> 2 FADD.
// No compares/selects/IMAD.WIDE. Partials to g_part (fixed-order combine).
// ---------------------------------------------------------------------------
__global__ void k_gather(const float* __restrict__ W_int,
                         float* __restrict__ out) {
    const int b = blockIdx.y;
    const int s = blockIdx.z;
    const int nwin = g_cnt[b] >> 4;
    const long long* __restrict__ lst = g_list[b];

    const int n2 = (blockIdx.x * 128 + threadIdx.x) * 2;  // column pair
    const char* base = (const char*)W_int + (size_t)n2 * 4;

    float ax0 = 0.f, ay0 = 0.f, ax1 = 0.f, ay1 = 0.f;
    float ax2 = 0.f, ay2 = 0.f, ax3 = 0.f, ay3 = 0.f;

    for (int j = s; j < nwin; j += NSPLIT) {
        const int k = j * 16;
        long long o[16];
#pragma unroll
        for (int u = 0; u < 16; u++) o[u] = __ldg(lst + k + u);
        float2 w[16];
#pragma unroll
        for (int u = 0; u < 16; u++)
            w[u] = __ldg((const float2*)(base + o[u]));
#pragma unroll
        for (int u = 0; u < 16; u += 4) {
            ax0 += w[u].x;     ay0 += w[u].y;
            ax1 += w[u + 1].x; ay1 += w[u + 1].y;
            ax2 += w[u + 2].x; ay2 += w[u + 2].y;
            ax3 += w[u + 3].x; ay3 += w[u + 3].y;
        }
    }

    float2 r;
    r.x = (ax0 + ax1) + (ax2 + ax3);
    r.y = (ay0 + ay1) + (ay2 + ay3);
    *(float2*)(&g_part[s][b][n2]) = r;
}

// ---------------------------------------------------------------------------
// Kernel 4: combine partials + leak/reset -> V_new (row 1), fixed order.
// Also re-zeroes the masks for the next call (they were consumed by compact).
// ---------------------------------------------------------------------------
__global__ void k_combine(const float* __restrict__ V, float* __restrict__ out) {
    int idx = blockIdx.x * blockDim.x + threadIdx.x;   // 0 .. B*N-1
    int b = idx >> 12;
    int n = idx & (NN - 1);
    float x = out[idx];                                 // X (row 0)
    float acc = 0.95f * V[idx] * (1.0f - x);
    acc += g_part[0][b][n];
    acc += g_part[1][b][n];
    acc += g_part[2][b][n];
    acc += g_part[3][b][n];
    out[BB * NN + idx] = acc;                           // row 1: V_new

    if (idx < NN)  g_mask_int[idx] = 0u;
    if (idx < NEE) g_mask_ext[idx] = 0u;
}

// ---------------------------------------------------------------------------
extern "C" void kernel_launch(void* const* d_in, const int* in_sizes, int n_in,
                              void* d_out, int out_size) {
    const float* V        = (const float*)d_in[0];   // [B,N]
    const float* a        = (const float*)d_in[1];   // [B,N]
    const float* Xd       = (const float*)d_in[2];   // [D,B,N]
    const float* Xext     = (const float*)d_in[3];   // [DE,B,NE]
    const float* W_int    = (const float*)d_in[4];   // [N,N]
    const float* W_ext    = (const float*)d_in[5];   // [NE,N]
    const float* dmap_int = (const float*)d_in[6];   // [D,N]
    const float* dmap_ext = (const float*)d_in[7];   // [DE,NE]
    float* out = (float*)d_out;                      // [3,B,N]

    k_spikemask<<<(BB * NN) / 256, 256>>>(V, a, Xd, Xext, dmap_int, dmap_ext, out);
    k_compact<<<BB, 256>>>(W_int, W_ext);
    dim3 grid(NN / 256, BB, NSPLIT);
    k_gather<<<grid, 128>>>(W_int, out);
    k_combine<<<(BB * NN) / 256, 256>>>(V, out);
}